// round 11
// baseline (speedup 1.0000x reference)
#include <cuda_runtime.h>
#include <cuda_bf16.h>
#include <cstdint>
#include <math.h>

// out = gelu_exact(x @ w1) @ w2 per expert.
// Split-bf16 scheme on HMMA (mma.sync m16n8k16 bf16):
//   C = Ah*Bh + Al*Bh + Ah*Bl   (drop Al*Bl, ~2^-18 relative)
// SMEM: 128B rows packing [hi 64B | lo 64B], SW128 XOR swizzle.
// 128x64 CTA tile, BK=64 (2 sub-blocks of 32), 2-stage pipeline, 2 CTAs/SM.

static constexpr int E = 8;
static constexpr int M = 2048;
static constexpr int D = 1024;
static constexpr int H = 4096;

// ---- device scratch (no runtime allocation allowed) ----
__device__ __align__(256) __nv_bfloat16 g_xh[(size_t)E * M * D];
__device__ __align__(256) __nv_bfloat16 g_xl[(size_t)E * M * D];
__device__ __align__(256) __nv_bfloat16 g_w1h[(size_t)E * H * D];  // [E][H][D] (transposed, K-major)
__device__ __align__(256) __nv_bfloat16 g_w1l[(size_t)E * H * D];
__device__ __align__(256) __nv_bfloat16 g_w2h[(size_t)E * D * H];  // [E][D][H] (transposed, K-major)
__device__ __align__(256) __nv_bfloat16 g_w2l[(size_t)E * D * H];
__device__ __align__(256) __nv_bfloat16 g_hh[(size_t)E * M * H];   // hidden hi [E][M][H]
__device__ __align__(256) __nv_bfloat16 g_hl[(size_t)E * M * H];   // hidden lo

// ======================= helpers =======================
__device__ __forceinline__ uint32_t smem_u32(const void* p) {
    uint32_t a;
    asm("{ .reg .u64 t; cvta.to.shared.u64 t, %1; cvt.u32.u64 %0, t; }" : "=r"(a) : "l"(p));
    return a;
}
__device__ __forceinline__ void cp16(uint32_t dst, const void* src) {
    asm volatile("cp.async.cg.shared.global [%0], [%1], 16;" :: "r"(dst), "l"(src));
}
#define CP_COMMIT() asm volatile("cp.async.commit_group;" ::: "memory")

__device__ __forceinline__ void ldsm_x4(uint32_t& r0, uint32_t& r1, uint32_t& r2,
                                        uint32_t& r3, uint32_t addr) {
    asm volatile("ldmatrix.sync.aligned.m8n8.x4.shared.b16 {%0,%1,%2,%3}, [%4];"
                 : "=r"(r0), "=r"(r1), "=r"(r2), "=r"(r3) : "r"(addr));
}
__device__ __forceinline__ void mma_bf16(float& d0, float& d1, float& d2, float& d3,
                                         uint32_t a0, uint32_t a1, uint32_t a2, uint32_t a3,
                                         uint32_t b0, uint32_t b1) {
    asm volatile(
        "mma.sync.aligned.m16n8k16.row.col.f32.bf16.bf16.f32 "
        "{%0,%1,%2,%3}, {%4,%5,%6,%7}, {%8,%9}, {%0,%1,%2,%3};"
        : "+f"(d0), "+f"(d1), "+f"(d2), "+f"(d3)
        : "r"(a0), "r"(a1), "r"(a2), "r"(a3), "r"(b0), "r"(b1));
}

// SW128 swizzle: XOR quad column (bits 6:4) with row mod 8 (bits 9:7)
__device__ __forceinline__ uint32_t swz(uint32_t off) { return off ^ ((off >> 3) & 0x70); }

__device__ __forceinline__ float gelu_exact(float x) {
    return 0.5f * x * (1.0f + erff(x * 0.7071067811865476f));
}

// ======================= conversion kernels =======================
__global__ void split_kernel(const float4* __restrict__ in,
                             __nv_bfloat16* __restrict__ hi,
                             __nv_bfloat16* __restrict__ lo) {
    size_t i = (size_t)blockIdx.x * blockDim.x + threadIdx.x;
    float4 v = in[i];
    float f[4] = {v.x, v.y, v.z, v.w};
    __nv_bfloat16 h[4], l[4];
#pragma unroll
    for (int j = 0; j < 4; j++) {
        h[j] = __float2bfloat16(f[j]);
        l[j] = __float2bfloat16(f[j] - __bfloat162float(h[j]));
    }
    *reinterpret_cast<uint2*>(hi + i * 4) = *reinterpret_cast<uint2*>(h);
    *reinterpret_cast<uint2*>(lo + i * 4) = *reinterpret_cast<uint2*>(l);
}

// in [R][C] per expert -> out [C][R] split to hi/lo
__global__ void transpose_split_kernel(const float* __restrict__ in,
                                       __nv_bfloat16* __restrict__ oh,
                                       __nv_bfloat16* __restrict__ ol,
                                       int R, int C) {
    __shared__ float tile[32][33];
    const float* src = in + (size_t)blockIdx.z * R * C;
    __nv_bfloat16* dh = oh + (size_t)blockIdx.z * R * C;
    __nv_bfloat16* dl = ol + (size_t)blockIdx.z * R * C;
    int c0 = blockIdx.x * 32, r0 = blockIdx.y * 32;
    int tx = threadIdx.x, ty = threadIdx.y;
#pragma unroll
    for (int i = ty; i < 32; i += 8)
        tile[i][tx] = src[(size_t)(r0 + i) * C + c0 + tx];
    __syncthreads();
#pragma unroll
    for (int i = ty; i < 32; i += 8) {
        float v = tile[tx][i];
        __nv_bfloat16 h = __float2bfloat16(v);
        float r = v - __bfloat162float(h);
        size_t o = (size_t)(c0 + i) * R + r0 + tx;
        dh[o] = h;
        dl[o] = __float2bfloat16(r);
    }
}

// ======================= HMMA GEMM =======================
// CTA tile 128x64, BK=64 (two 32-k sub-blocks). 8 warps (4x2), warp tile 32x32.
// Per sub-block: A tile (128 rows x [Ah|Al] 128B) = 16KB, B tile (64 rows x 128B) = 8KB.
// Stage = 2 sub-blocks = 48KB. 2 stages = 96KB/CTA, 2 CTAs/SM.
static constexpr int BK = 64;
static constexpr int A_TILE_BYTES = 128 * 128;               // 16384
static constexpr int B_TILE_BYTES = 64 * 128;                // 8192
static constexpr int B_OFF = A_TILE_BYTES;
static constexpr int SUB_BYTES = A_TILE_BYTES + B_TILE_BYTES;    // 24576
static constexpr int STAGE_BYTES = 2 * SUB_BYTES;                // 49152
static constexpr int STAGES = 2;
static constexpr int SMEM_BYTES = STAGES * STAGE_BYTES;          // 98304

template <bool GELU_SPLIT>
__global__ __launch_bounds__(256, 2)
void hmma_gemm_kernel(const __nv_bfloat16* __restrict__ Ah,
                      const __nv_bfloat16* __restrict__ Al,
                      const __nv_bfloat16* __restrict__ Bh,
                      const __nv_bfloat16* __restrict__ Bl,
                      float* __restrict__ Cout,
                      __nv_bfloat16* __restrict__ Ch,
                      __nv_bfloat16* __restrict__ Cl,
                      int Mdim, int Ndim, int Kdim) {
    extern __shared__ char smem[];
    const uint32_t sb = smem_u32(smem);

    const int tid = threadIdx.x;
    const int wid = tid >> 5;
    const int lane = tid & 31;
    const int e = blockIdx.z;
    const int brow = blockIdx.y * 128;
    const int bcol = blockIdx.x * 64;

    const size_t mk = (size_t)Mdim * Kdim, nk = (size_t)Ndim * Kdim;
    const size_t mn = (size_t)Mdim * Ndim;
    Ah += (size_t)e * mk; Al += (size_t)e * mk;
    Bh += (size_t)e * nk; Bl += (size_t)e * nk;
    if (GELU_SPLIT) { Ch += (size_t)e * mn; Cl += (size_t)e * mn; }
    else            { Cout += (size_t)e * mn; }

    const int warp_m = (wid >> 1) * 32;   // 0,32,64,96
    const int warp_n = (wid & 1) * 32;    // 0,32

    // per-lane ldmatrix row/quad decomposition
    const int lr = lane & 7, lg = lane >> 3;
    const int a_row = lr + (lg & 1) * 8;     // row within 16-row tile
    const int a_q   = lg >> 1;               // k-half quad
    const int b_row = lr + (lg >> 1) * 8;    // row within 16-n-row pair
    const int b_q   = lg & 1;

    float acc[2][4][4];
#pragma unroll
    for (int i = 0; i < 2; i++)
#pragma unroll
        for (int j = 0; j < 4; j++)
#pragma unroll
            for (int r = 0; r < 4; r++) acc[i][j][r] = 0.0f;

    const int NK = Kdim / BK;

    // Per stage: 2 sub-blocks x (A 1024 quads + B 512 quads) = 3072 quads; 12 cp16/thread.
    auto load_stage = [&](int kc, int stage) {
        const uint32_t stg = sb + stage * STAGE_BYTES;
#pragma unroll
        for (int kb = 0; kb < 2; kb++) {
            const int k0 = kc * BK + kb * 32;
            const uint32_t st = stg + kb * SUB_BYTES;
#pragma unroll
            for (int p = 0; p < 4; p++) {   // A: 1024 quads
                const int qi = tid + p * 256;
                const int r = qi >> 3, c = qi & 7;
                const int csel = (c & 3) * 8;
                cp16(st + swz(r * 128 + c * 16),
                     (c < 4 ? Ah : Al) + (size_t)(brow + r) * Kdim + k0 + csel);
            }
#pragma unroll
            for (int p = 0; p < 2; p++) {   // B: 512 quads
                const int qi = tid + p * 256;
                const int r = qi >> 3, c = qi & 7;
                const int csel = (c & 3) * 8;
                cp16(st + B_OFF + swz(r * 128 + c * 16),
                     (c < 4 ? Bh : Bl) + (size_t)(bcol + r) * Kdim + k0 + csel);
            }
        }
        CP_COMMIT();
    };

    load_stage(0, 0);

    for (int k = 0; k < NK; k++) {
        const int s = k & 1;
        const uint32_t stg = sb + s * STAGE_BYTES;
        // Own loads for chunk k done:
        asm volatile("cp.async.wait_group 0;" ::: "memory");
        // Everyone's loads done AND everyone finished reading the other stage:
        __syncthreads();
        // Prefetch next chunk into the other stage (safe: barrier above).
        if (k + 1 < NK) load_stage(k + 1, s ^ 1);

#pragma unroll
        for (int kb = 0; kb < 2; kb++) {
            const uint32_t st = stg + kb * SUB_BYTES;
#pragma unroll
            for (int ks = 0; ks < 2; ks++) {
                uint32_t ah[2][4], al[2][4], bh[4][2], bl[4][2];
                const int aq_h = 2 * ks + a_q;        // hi quad col (0..3)
                const int bq_h = 2 * ks + b_q;
#pragma unroll
                for (int i = 0; i < 2; i++) {
                    const uint32_t arow_off = (warp_m + a_row + i * 16) * 128;
                    ldsm_x4(ah[i][0], ah[i][1], ah[i][2], ah[i][3],
                            st + swz(arow_off + aq_h * 16));
                    ldsm_x4(al[i][0], al[i][1], al[i][2], al[i][3],
                            st + swz(arow_off + (aq_h + 4) * 16));
                }
#pragma unroll
                for (int jp = 0; jp < 2; jp++) {
                    const uint32_t brow_off = (warp_n + b_row + jp * 16) * 128;
                    ldsm_x4(bh[2 * jp][0], bh[2 * jp][1], bh[2 * jp + 1][0], bh[2 * jp + 1][1],
                            st + B_OFF + swz(brow_off + bq_h * 16));
                    ldsm_x4(bl[2 * jp][0], bl[2 * jp][1], bl[2 * jp + 1][0], bl[2 * jp + 1][1],
                            st + B_OFF + swz(brow_off + (bq_h + 4) * 16));
                }
                // plane-outer ordering: 8 independent acc chains between dependent MMAs
#pragma unroll
                for (int i = 0; i < 2; i++)
#pragma unroll
                    for (int j = 0; j < 4; j++)
                        mma_bf16(acc[i][j][0], acc[i][j][1], acc[i][j][2], acc[i][j][3],
                                 ah[i][0], ah[i][1], ah[i][2], ah[i][3], bh[j][0], bh[j][1]);
#pragma unroll
                for (int i = 0; i < 2; i++)
#pragma unroll
                    for (int j = 0; j < 4; j++)
                        mma_bf16(acc[i][j][0], acc[i][j][1], acc[i][j][2], acc[i][j][3],
                                 al[i][0], al[i][1], al[i][2], al[i][3], bh[j][0], bh[j][1]);
#pragma unroll
                for (int i = 0; i < 2; i++)
#pragma unroll
                    for (int j = 0; j < 4; j++)
                        mma_bf16(acc[i][j][0], acc[i][j][1], acc[i][j][2], acc[i][j][3],
                                 ah[i][0], ah[i][1], ah[i][2], ah[i][3], bl[j][0], bl[j][1]);
            }
        }
    }

    // ---- epilogue ----
    const int lrow = lane >> 2;          // 0..7
    const int lcol = (lane & 3) * 2;     // 0,2,4,6
#pragma unroll
    for (int i = 0; i < 2; i++) {
#pragma unroll
        for (int hh = 0; hh < 2; hh++) {
            const size_t row = (size_t)(brow + warp_m + i * 16 + lrow + hh * 8);
#pragma unroll
            for (int j = 0; j < 4; j++) {
                const size_t col = (size_t)(bcol + warp_n + j * 8 + lcol);
                float v0 = acc[i][j][2 * hh];
                float v1 = acc[i][j][2 * hh + 1];
                if (GELU_SPLIT) {
                    v0 = gelu_exact(v0);
                    v1 = gelu_exact(v1);
                    __nv_bfloat16 h0 = __float2bfloat16(v0);
                    __nv_bfloat16 h1 = __float2bfloat16(v1);
                    __nv_bfloat162 hp; hp.x = h0; hp.y = h1;
                    __nv_bfloat162 lp;
                    lp.x = __float2bfloat16(v0 - __bfloat162float(h0));
                    lp.y = __float2bfloat16(v1 - __bfloat162float(h1));
                    *reinterpret_cast<uint32_t*>(Ch + row * Ndim + col) =
                        *reinterpret_cast<uint32_t*>(&hp);
                    *reinterpret_cast<uint32_t*>(Cl + row * Ndim + col) =
                        *reinterpret_cast<uint32_t*>(&lp);
                } else {
                    float2 o; o.x = v0; o.y = v1;
                    *reinterpret_cast<float2*>(Cout + row * Ndim + col) = o;
                }
            }
        }
    }
}

// ======================= launch =======================
extern "C" void kernel_launch(void* const* d_in, const int* in_sizes, int n_in,
                              void* d_out, int out_size) {
    const float* x  = (const float*)d_in[0];
    const float* w1 = (const float*)d_in[1];
    const float* w2 = (const float*)d_in[2];
    float* out = (float*)d_out;
    (void)in_sizes; (void)n_in; (void)out_size;

    cudaFuncSetAttribute(hmma_gemm_kernel<true>,
                         cudaFuncAttributeMaxDynamicSharedMemorySize, SMEM_BYTES);
    cudaFuncSetAttribute(hmma_gemm_kernel<false>,
                         cudaFuncAttributeMaxDynamicSharedMemorySize, SMEM_BYTES);

    __nv_bfloat16 *xh, *xl, *w1h, *w1l, *w2h, *w2l, *hh, *hl;
    cudaGetSymbolAddress((void**)&xh,  g_xh);
    cudaGetSymbolAddress((void**)&xl,  g_xl);
    cudaGetSymbolAddress((void**)&w1h, g_w1h);
    cudaGetSymbolAddress((void**)&w1l, g_w1l);
    cudaGetSymbolAddress((void**)&w2h, g_w2h);
    cudaGetSymbolAddress((void**)&w2l, g_w2l);
    cudaGetSymbolAddress((void**)&hh,  g_hh);
    cudaGetSymbolAddress((void**)&hl,  g_hl);

    // 1) split x
    {
        size_t n4 = (size_t)E * M * D / 4;
        split_kernel<<<(unsigned)(n4 / 256), 256>>>((const float4*)x, xh, xl);
    }
    // 2) transpose+split w1: [E][D][H] -> [E][H][D]
    {
        dim3 grid(H / 32, D / 32, E), blk(32, 8);
        transpose_split_kernel<<<grid, blk>>>(w1, w1h, w1l, D, H);
    }
    // 3) transpose+split w2: [E][H][D] -> [E][D][H]
    {
        dim3 grid(D / 32, H / 32, E), blk(32, 8);
        transpose_split_kernel<<<grid, blk>>>(w2, w2h, w2l, H, D);
    }
    // 4) GEMM1 + GELU + split -> hidden planes  (M x H, K = D)
    {
        dim3 grid(H / 64, M / 128, E);
        hmma_gemm_kernel<true><<<grid, 256, SMEM_BYTES>>>(
            xh, xl, w1h, w1l, nullptr, hh, hl, M, H, D);
    }
    // 5) GEMM2 -> out  (M x D, K = H)
    {
        dim3 grid(D / 64, M / 128, E);
        hmma_gemm_kernel<false><<<grid, 256, SMEM_BYTES>>>(
            hh, hl, w2h, w2l, out, nullptr, nullptr, M, D, H);
    }
}

// round 12
// speedup vs baseline: 1.4857x; 1.4857x over previous
#include <cuda_runtime.h>
#include <cuda_fp16.h>
#include <cstdint>
#include <math.h>

// out = gelu_exact(x @ w1) @ w2 per expert.
// 2-plane fp16 scheme on HMMA (mma.sync m16n8k16 f16):
//   activations rounded to fp16 (1 plane), weights split Wh+Wl (fp16 hi/lo)
//   C = A*Wh + A*Wl ; error ~ activation rounding (~2e-4 rel), weights ~1e-6.

static constexpr int E = 8;
static constexpr int M = 2048;
static constexpr int D = 1024;
static constexpr int H = 4096;

// ---- device scratch (no runtime allocation allowed) ----
__device__ __align__(256) __half g_x  [(size_t)E * M * D];  // x rounded to fp16
__device__ __align__(256) __half g_w1h[(size_t)E * H * D];  // [E][H][D] K-major hi
__device__ __align__(256) __half g_w1l[(size_t)E * H * D];  // lo
__device__ __align__(256) __half g_w2h[(size_t)E * D * H];  // [E][D][H] K-major hi
__device__ __align__(256) __half g_w2l[(size_t)E * D * H];  // lo
__device__ __align__(256) __half g_h  [(size_t)E * M * H];  // hidden fp16 [E][M][H]

// ======================= helpers =======================
__device__ __forceinline__ uint32_t smem_u32(const void* p) {
    uint32_t a;
    asm("{ .reg .u64 t; cvta.to.shared.u64 t, %1; cvt.u32.u64 %0, t; }" : "=r"(a) : "l"(p));
    return a;
}
__device__ __forceinline__ void cp16(uint32_t dst, const void* src) {
    asm volatile("cp.async.cg.shared.global [%0], [%1], 16;" :: "r"(dst), "l"(src));
}
#define CP_COMMIT() asm volatile("cp.async.commit_group;" ::: "memory")

__device__ __forceinline__ void ldsm_x4(uint32_t& r0, uint32_t& r1, uint32_t& r2,
                                        uint32_t& r3, uint32_t addr) {
    asm volatile("ldmatrix.sync.aligned.m8n8.x4.shared.b16 {%0,%1,%2,%3}, [%4];"
                 : "=r"(r0), "=r"(r1), "=r"(r2), "=r"(r3) : "r"(addr));
}
__device__ __forceinline__ void mma_f16(float& d0, float& d1, float& d2, float& d3,
                                        uint32_t a0, uint32_t a1, uint32_t a2, uint32_t a3,
                                        uint32_t b0, uint32_t b1) {
    asm volatile(
        "mma.sync.aligned.m16n8k16.row.col.f32.f16.f16.f32 "
        "{%0,%1,%2,%3}, {%4,%5,%6,%7}, {%8,%9}, {%0,%1,%2,%3};"
        : "+f"(d0), "+f"(d1), "+f"(d2), "+f"(d3)
        : "r"(a0), "r"(a1), "r"(a2), "r"(a3), "r"(b0), "r"(b1));
}

// SW128 swizzle: XOR quad column (bits 6:4) with row mod 8 (bits 9:7)
__device__ __forceinline__ uint32_t swz(uint32_t off) { return off ^ ((off >> 3) & 0x70); }

__device__ __forceinline__ float gelu_exact(float x) {
    return 0.5f * x * (1.0f + erff(x * 0.7071067811865476f));
}

// ======================= conversion kernels =======================
// round fp32 -> fp16, 4 elems/thread
__global__ void round_kernel(const float4* __restrict__ in, __half* __restrict__ out) {
    size_t i = (size_t)blockIdx.x * blockDim.x + threadIdx.x;
    float4 v = in[i];
    __half h[4] = {__float2half_rn(v.x), __float2half_rn(v.y),
                   __float2half_rn(v.z), __float2half_rn(v.w)};
    *reinterpret_cast<uint2*>(out + i * 4) = *reinterpret_cast<const uint2*>(h);
}

// in [R][C] per expert -> out [C][R], split to fp16 hi/lo
__global__ void transpose_split_kernel(const float* __restrict__ in,
                                       __half* __restrict__ oh,
                                       __half* __restrict__ ol,
                                       int R, int C) {
    __shared__ float tile[32][33];
    const float* src = in + (size_t)blockIdx.z * R * C;
    __half* dh = oh + (size_t)blockIdx.z * R * C;
    __half* dl = ol + (size_t)blockIdx.z * R * C;
    int c0 = blockIdx.x * 32, r0 = blockIdx.y * 32;
    int tx = threadIdx.x, ty = threadIdx.y;
#pragma unroll
    for (int i = ty; i < 32; i += 8)
        tile[i][tx] = src[(size_t)(r0 + i) * C + c0 + tx];
    __syncthreads();
#pragma unroll
    for (int i = ty; i < 32; i += 8) {
        float v = tile[tx][i];
        __half h = __float2half_rn(v);
        float r = v - __half2float(h);
        size_t o = (size_t)(c0 + i) * R + r0 + tx;
        dh[o] = h;
        dl[o] = __float2half_rn(r);
    }
}

// ======================= HMMA GEMM =======================
// CTA tile 128x128, BK=64. 8 warps (2m x 4n), warp tile 64x32. 2 CTAs/SM.
// SMEM per stage:
//   A: 128 rows x 128B  (k0..63 fp16, single plane), SW128.          16 KB
//   B: 2 sub-blocks (k32 each), 128 rows x [Wh 64B | Wl 64B], SW128. 32 KB
static constexpr int BK = 64;
static constexpr int A_BYTES = 128 * 128;                 // 16384
static constexpr int B_SUB_BYTES = 128 * 128;             // 16384 per k32 sub-block
static constexpr int B_OFF = A_BYTES;
static constexpr int STAGE_BYTES = A_BYTES + 2 * B_SUB_BYTES;  // 49152
static constexpr int STAGES = 2;
static constexpr int SMEM_BYTES = STAGES * STAGE_BYTES;        // 98304

template <bool GELU_HALF_OUT>
__global__ __launch_bounds__(256, 2)
void hmma_gemm_kernel(const __half* __restrict__ A,
                      const __half* __restrict__ Bh,
                      const __half* __restrict__ Bl,
                      float* __restrict__ Cout,
                      __half* __restrict__ Chalf,
                      int Mdim, int Ndim, int Kdim) {
    extern __shared__ char smem[];
    const uint32_t sb = smem_u32(smem);

    const int tid = threadIdx.x;
    const int wid = tid >> 5;
    const int lane = tid & 31;
    const int e = blockIdx.z;
    const int brow = blockIdx.y * 128;
    const int bcol = blockIdx.x * 128;

    const size_t mk = (size_t)Mdim * Kdim, nk = (size_t)Ndim * Kdim;
    const size_t mn = (size_t)Mdim * Ndim;
    A += (size_t)e * mk;
    Bh += (size_t)e * nk; Bl += (size_t)e * nk;
    if (GELU_HALF_OUT) Chalf += (size_t)e * mn;
    else               Cout  += (size_t)e * mn;

    const int warp_m = (wid >> 2) * 64;   // 0, 64
    const int warp_n = (wid & 3) * 32;    // 0,32,64,96

    // per-lane ldmatrix row/quad decomposition
    const int lr = lane & 7, lg = lane >> 3;
    const int a_row = lr + (lg & 1) * 8;     // row within 16-row tile
    const int a_q   = lg >> 1;               // k8-half within k16
    const int b_row = lr + (lg >> 1) * 8;    // row within 16-n-row pair
    const int b_q   = lg & 1;

    float acc[4][4][4];
#pragma unroll
    for (int i = 0; i < 4; i++)
#pragma unroll
        for (int j = 0; j < 4; j++)
#pragma unroll
            for (int r = 0; r < 4; r++) acc[i][j][r] = 0.0f;

    const int NK = Kdim / BK;

    // STS: A 1024 quads (4/thread), B 2 sub-blocks x 1024 quads (8/thread).
    auto load_stage = [&](int kc, int stage) {
        const int k0 = kc * BK;
        const uint32_t stg = sb + stage * STAGE_BYTES;
#pragma unroll
        for (int p = 0; p < 4; p++) {   // A plane: rows x 8 quads = k0..63
            const int qi = tid + p * 256;
            const int r = qi >> 3, c = qi & 7;
            cp16(stg + swz(r * 128 + c * 16),
                 A + (size_t)(brow + r) * Kdim + k0 + c * 8);
        }
#pragma unroll
        for (int kb = 0; kb < 2; kb++) {
            const uint32_t stb = stg + B_OFF + kb * B_SUB_BYTES;
            const int kk = k0 + kb * 32;
#pragma unroll
            for (int p = 0; p < 4; p++) {
                const int qi = tid + p * 256;
                const int r = qi >> 3, c = qi & 7;
                const int csel = (c & 3) * 8;
                cp16(stb + swz(r * 128 + c * 16),
                     (c < 4 ? Bh : Bl) + (size_t)(bcol + r) * Kdim + kk + csel);
            }
        }
        CP_COMMIT();
    };

    load_stage(0, 0);

    for (int k = 0; k < NK; k++) {
        const int s = k & 1;
        const uint32_t stg = sb + s * STAGE_BYTES;
        asm volatile("cp.async.wait_group 0;" ::: "memory");
        __syncthreads();
        if (k + 1 < NK) load_stage(k + 1, s ^ 1);

#pragma unroll
        for (int s16 = 0; s16 < 4; s16++) {       // four k16 steps in BK=64
            const int aq = 2 * s16 + a_q;          // A quad 0..7
            const int kb = s16 >> 1, ksb = s16 & 1;
            const int bqh = 2 * ksb + b_q;         // B hi quad 0..3
            const uint32_t stb = stg + B_OFF + kb * B_SUB_BYTES;

            uint32_t bh[4][2], bl[4][2];
#pragma unroll
            for (int jp = 0; jp < 2; jp++) {
                const uint32_t brow_off = (warp_n + b_row + jp * 16) * 128;
                ldsm_x4(bh[2 * jp][0], bh[2 * jp][1], bh[2 * jp + 1][0], bh[2 * jp + 1][1],
                        stb + swz(brow_off + bqh * 16));
                ldsm_x4(bl[2 * jp][0], bl[2 * jp][1], bl[2 * jp + 1][0], bl[2 * jp + 1][1],
                        stb + swz(brow_off + (bqh + 4) * 16));
            }
            // A in two i-pairs to bound register pressure
#pragma unroll
            for (int ip = 0; ip < 2; ip++) {
                uint32_t a[2][4];
#pragma unroll
                for (int ii = 0; ii < 2; ii++) {
                    const int i = 2 * ip + ii;
                    ldsm_x4(a[ii][0], a[ii][1], a[ii][2], a[ii][3],
                            stg + swz((warp_m + a_row + i * 16) * 128 + aq * 16));
                }
                // plane-outer: 8 independent acc chains between dependent MMAs
#pragma unroll
                for (int ii = 0; ii < 2; ii++)
#pragma unroll
                    for (int j = 0; j < 4; j++) {
                        const int i = 2 * ip + ii;
                        mma_f16(acc[i][j][0], acc[i][j][1], acc[i][j][2], acc[i][j][3],
                                a[ii][0], a[ii][1], a[ii][2], a[ii][3], bh[j][0], bh[j][1]);
                    }
#pragma unroll
                for (int ii = 0; ii < 2; ii++)
#pragma unroll
                    for (int j = 0; j < 4; j++) {
                        const int i = 2 * ip + ii;
                        mma_f16(acc[i][j][0], acc[i][j][1], acc[i][j][2], acc[i][j][3],
                                a[ii][0], a[ii][1], a[ii][2], a[ii][3], bl[j][0], bl[j][1]);
                    }
            }
        }
    }

    // ---- epilogue ----
    const int lrow = lane >> 2;          // 0..7
    const int lcol = (lane & 3) * 2;     // 0,2,4,6
#pragma unroll
    for (int i = 0; i < 4; i++) {
#pragma unroll
        for (int hh = 0; hh < 2; hh++) {
            const size_t row = (size_t)(brow + warp_m + i * 16 + lrow + hh * 8);
#pragma unroll
            for (int j = 0; j < 4; j++) {
                const size_t col = (size_t)(bcol + warp_n + j * 8 + lcol);
                float v0 = acc[i][j][2 * hh];
                float v1 = acc[i][j][2 * hh + 1];
                if (GELU_HALF_OUT) {
                    __half h[2] = {__float2half_rn(gelu_exact(v0)),
                                   __float2half_rn(gelu_exact(v1))};
                    *reinterpret_cast<uint32_t*>(Chalf + row * Ndim + col) =
                        *reinterpret_cast<const uint32_t*>(h);
                } else {
                    float2 o; o.x = v0; o.y = v1;
                    *reinterpret_cast<float2*>(Cout + row * Ndim + col) = o;
                }
            }
        }
    }
}

// ======================= launch =======================
extern "C" void kernel_launch(void* const* d_in, const int* in_sizes, int n_in,
                              void* d_out, int out_size) {
    const float* x  = (const float*)d_in[0];
    const float* w1 = (const float*)d_in[1];
    const float* w2 = (const float*)d_in[2];
    float* out = (float*)d_out;
    (void)in_sizes; (void)n_in; (void)out_size;

    cudaFuncSetAttribute(hmma_gemm_kernel<true>,
                         cudaFuncAttributeMaxDynamicSharedMemorySize, SMEM_BYTES);
    cudaFuncSetAttribute(hmma_gemm_kernel<false>,
                         cudaFuncAttributeMaxDynamicSharedMemorySize, SMEM_BYTES);

    __half *xh, *w1h, *w1l, *w2h, *w2l, *hid;
    cudaGetSymbolAddress((void**)&xh,  g_x);
    cudaGetSymbolAddress((void**)&w1h, g_w1h);
    cudaGetSymbolAddress((void**)&w1l, g_w1l);
    cudaGetSymbolAddress((void**)&w2h, g_w2h);
    cudaGetSymbolAddress((void**)&w2l, g_w2l);
    cudaGetSymbolAddress((void**)&hid, g_h);

    // 1) round x -> fp16
    {
        size_t n4 = (size_t)E * M * D / 4;
        round_kernel<<<(unsigned)(n4 / 256), 256>>>((const float4*)x, xh);
    }
    // 2) transpose+split w1: [E][D][H] -> [E][H][D] fp16 hi/lo
    {
        dim3 grid(H / 32, D / 32, E), blk(32, 8);
        transpose_split_kernel<<<grid, blk>>>(w1, w1h, w1l, D, H);
    }
    // 3) transpose+split w2: [E][H][D] -> [E][D][H] fp16 hi/lo
    {
        dim3 grid(D / 32, H / 32, E), blk(32, 8);
        transpose_split_kernel<<<grid, blk>>>(w2, w2h, w2l, H, D);
    }
    // 4) GEMM1 + GELU -> hidden fp16  (M x H, K = D)
    {
        dim3 grid(H / 128, M / 128, E);
        hmma_gemm_kernel<true><<<grid, 256, SMEM_BYTES>>>(
            xh, w1h, w1l, nullptr, hid, M, H, D);
    }
    // 5) GEMM2 -> out fp32  (M x D, K = H)
    {
        dim3 grid(D / 128, M / 128, E);
        hmma_gemm_kernel<false><<<grid, 256, SMEM_BYTES>>>(
            hid, w2h, w2l, out, nullptr, M, D, H);
    }
}

// round 13
// speedup vs baseline: 2.3337x; 1.5708x over previous
#include <cuda_runtime.h>
#include <cuda_fp16.h>
#include <cstdint>
#include <math.h>

// out = gelu_exact(x @ w1) @ w2 per expert.
// Plain fp16 HMMA (mma.sync m16n8k16 f16, fp32 accum), all operands rounded
// to fp16. Error budget: x ~1.5e-4, w1 ~1.5e-4, hidden ~2e-4 (round+gelu),
// w2 ~1.5e-4 -> ~3.7e-4 total, under the 1e-3 threshold with margin.

static constexpr int E = 8;
static constexpr int M = 2048;
static constexpr int D = 1024;
static constexpr int H = 4096;

// ---- device scratch (no runtime allocation allowed) ----
__device__ __align__(256) __half g_x [(size_t)E * M * D];  // x fp16
__device__ __align__(256) __half g_w1[(size_t)E * H * D];  // [E][H][D] K-major
__device__ __align__(256) __half g_w2[(size_t)E * D * H];  // [E][D][H] K-major
__device__ __align__(256) __half g_h [(size_t)E * M * H];  // hidden fp16 [E][M][H]

// ======================= helpers =======================
__device__ __forceinline__ uint32_t smem_u32(const void* p) {
    uint32_t a;
    asm("{ .reg .u64 t; cvta.to.shared.u64 t, %1; cvt.u32.u64 %0, t; }" : "=r"(a) : "l"(p));
    return a;
}
__device__ __forceinline__ void cp16(uint32_t dst, const void* src) {
    asm volatile("cp.async.cg.shared.global [%0], [%1], 16;" :: "r"(dst), "l"(src));
}
#define CP_COMMIT() asm volatile("cp.async.commit_group;" ::: "memory")

__device__ __forceinline__ void ldsm_x4(uint32_t& r0, uint32_t& r1, uint32_t& r2,
                                        uint32_t& r3, uint32_t addr) {
    asm volatile("ldmatrix.sync.aligned.m8n8.x4.shared.b16 {%0,%1,%2,%3}, [%4];"
                 : "=r"(r0), "=r"(r1), "=r"(r2), "=r"(r3) : "r"(addr));
}
__device__ __forceinline__ void mma_f16(float& d0, float& d1, float& d2, float& d3,
                                        uint32_t a0, uint32_t a1, uint32_t a2, uint32_t a3,
                                        uint32_t b0, uint32_t b1) {
    asm volatile(
        "mma.sync.aligned.m16n8k16.row.col.f32.f16.f16.f32 "
        "{%0,%1,%2,%3}, {%4,%5,%6,%7}, {%8,%9}, {%0,%1,%2,%3};"
        : "+f"(d0), "+f"(d1), "+f"(d2), "+f"(d3)
        : "r"(a0), "r"(a1), "r"(a2), "r"(a3), "r"(b0), "r"(b1));
}

// SW128 swizzle: XOR quad column (bits 6:4) with row mod 8 (bits 9:7)
__device__ __forceinline__ uint32_t swz(uint32_t off) { return off ^ ((off >> 3) & 0x70); }

__device__ __forceinline__ float gelu_exact(float x) {
    return 0.5f * x * (1.0f + erff(x * 0.7071067811865476f));
}

// ======================= conversion kernels =======================
// round fp32 -> fp16, 4 elems/thread
__global__ void round_kernel(const float4* __restrict__ in, __half* __restrict__ out) {
    size_t i = (size_t)blockIdx.x * blockDim.x + threadIdx.x;
    float4 v = in[i];
    __half h[4] = {__float2half_rn(v.x), __float2half_rn(v.y),
                   __float2half_rn(v.z), __float2half_rn(v.w)};
    *reinterpret_cast<uint2*>(out + i * 4) = *reinterpret_cast<const uint2*>(h);
}

// in [R][C] per expert -> out [C][R] fp16
__global__ void transpose_round_kernel(const float* __restrict__ in,
                                       __half* __restrict__ o,
                                       int R, int C) {
    __shared__ float tile[32][33];
    const float* src = in + (size_t)blockIdx.z * R * C;
    __half* dst = o + (size_t)blockIdx.z * R * C;
    int c0 = blockIdx.x * 32, r0 = blockIdx.y * 32;
    int tx = threadIdx.x, ty = threadIdx.y;
#pragma unroll
    for (int i = ty; i < 32; i += 8)
        tile[i][tx] = src[(size_t)(r0 + i) * C + c0 + tx];
    __syncthreads();
#pragma unroll
    for (int i = ty; i < 32; i += 8)
        dst[(size_t)(c0 + i) * R + r0 + tx] = __float2half_rn(tile[tx][i]);
}

// ======================= HMMA GEMM =======================
// CTA tile 128x256, BK=64. 8 warps (2m x 4n), warp tile 64x64. 1 CTA/SM.
// SMEM per stage: A 128 rows x 128B = 16KB, B 256 rows x 128B = 32KB.
// 2 stages = 96KB.
static constexpr int BK = 64;
static constexpr int BN = 256;
static constexpr int A_BYTES = 128 * 128;                 // 16384
static constexpr int B_BYTES = 256 * 128;                 // 32768
static constexpr int B_OFF = A_BYTES;
static constexpr int STAGE_BYTES = A_BYTES + B_BYTES;     // 49152
static constexpr int SMEM_BYTES = 2 * STAGE_BYTES;        // 98304

template <bool GELU_HALF_OUT>
__global__ __launch_bounds__(256, 1)
void hmma_gemm_kernel(const __half* __restrict__ A,
                      const __half* __restrict__ B,
                      float* __restrict__ Cout,
                      __half* __restrict__ Chalf,
                      int Mdim, int Ndim, int Kdim) {
    extern __shared__ char smem[];
    const uint32_t sb = smem_u32(smem);

    const int tid = threadIdx.x;
    const int wid = tid >> 5;
    const int lane = tid & 31;
    const int e = blockIdx.z;
    const int brow = blockIdx.y * 128;
    const int bcol = blockIdx.x * BN;

    const size_t mk = (size_t)Mdim * Kdim, nk = (size_t)Ndim * Kdim;
    const size_t mn = (size_t)Mdim * Ndim;
    A += (size_t)e * mk;
    B += (size_t)e * nk;
    if (GELU_HALF_OUT) Chalf += (size_t)e * mn;
    else               Cout  += (size_t)e * mn;

    const int warp_m = (wid >> 2) * 64;   // 0, 64
    const int warp_n = (wid & 3) * 64;    // 0,64,128,192

    // per-lane ldmatrix row/quad decomposition
    const int lr = lane & 7, lg = lane >> 3;
    const int a_row = lr + (lg & 1) * 8;     // row within 16-row tile
    const int a_q   = lg >> 1;               // k8-half within k16
    const int b_row = lr + (lg >> 1) * 8;    // row within 16-n-row pair
    const int b_q   = lg & 1;

    float acc[4][8][4];
#pragma unroll
    for (int i = 0; i < 4; i++)
#pragma unroll
        for (int j = 0; j < 8; j++)
#pragma unroll
            for (int r = 0; r < 4; r++) acc[i][j][r] = 0.0f;

    const int NK = Kdim / BK;

    // STS per stage: A 1024 quads (4/thread) + B 2048 quads (8/thread).
    auto load_stage = [&](int kc, int stage) {
        const int k0 = kc * BK;
        const uint32_t stg = sb + stage * STAGE_BYTES;
#pragma unroll
        for (int p = 0; p < 4; p++) {
            const int qi = tid + p * 256;
            const int r = qi >> 3, c = qi & 7;
            cp16(stg + swz(r * 128 + c * 16),
                 A + (size_t)(brow + r) * Kdim + k0 + c * 8);
        }
#pragma unroll
        for (int p = 0; p < 8; p++) {
            const int qi = tid + p * 256;
            const int r = qi >> 3, c = qi & 7;
            cp16(stg + B_OFF + swz(r * 128 + c * 16),
                 B + (size_t)(bcol + r) * Kdim + k0 + c * 8);
        }
        CP_COMMIT();
    };

    load_stage(0, 0);

    for (int k = 0; k < NK; k++) {
        const int s = k & 1;
        const uint32_t stg = sb + s * STAGE_BYTES;
        asm volatile("cp.async.wait_group 0;" ::: "memory");
        __syncthreads();
        if (k + 1 < NK) load_stage(k + 1, s ^ 1);

#pragma unroll
        for (int s16 = 0; s16 < 4; s16++) {       // four k16 steps in BK=64
            const int aq = 2 * s16 + a_q;          // A quad col 0..7
            const int bq = 2 * s16 + b_q;          // B quad col 0..7

            uint32_t b[8][2];
#pragma unroll
            for (int jp = 0; jp < 4; jp++) {
                const uint32_t brow_off = (warp_n + b_row + jp * 16) * 128;
                ldsm_x4(b[2 * jp][0], b[2 * jp][1], b[2 * jp + 1][0], b[2 * jp + 1][1],
                        stg + B_OFF + swz(brow_off + bq * 16));
            }
            uint32_t a[4][4];
#pragma unroll
            for (int i = 0; i < 4; i++)
                ldsm_x4(a[i][0], a[i][1], a[i][2], a[i][3],
                        stg + swz((warp_m + a_row + i * 16) * 128 + aq * 16));
            // 32 independent MMAs per k16 step
#pragma unroll
            for (int i = 0; i < 4; i++)
#pragma unroll
                for (int j = 0; j < 8; j++)
                    mma_f16(acc[i][j][0], acc[i][j][1], acc[i][j][2], acc[i][j][3],
                            a[i][0], a[i][1], a[i][2], a[i][3], b[j][0], b[j][1]);
        }
    }

    // ---- epilogue ----
    const int lrow = lane >> 2;          // 0..7
    const int lcol = (lane & 3) * 2;     // 0,2,4,6
#pragma unroll
    for (int i = 0; i < 4; i++) {
#pragma unroll
        for (int hh = 0; hh < 2; hh++) {
            const size_t row = (size_t)(brow + warp_m + i * 16 + lrow + hh * 8);
#pragma unroll
            for (int j = 0; j < 8; j++) {
                const size_t col = (size_t)(bcol + warp_n + j * 8 + lcol);
                float v0 = acc[i][j][2 * hh];
                float v1 = acc[i][j][2 * hh + 1];
                if (GELU_HALF_OUT) {
                    __half h[2] = {__float2half_rn(gelu_exact(v0)),
                                   __float2half_rn(gelu_exact(v1))};
                    *reinterpret_cast<uint32_t*>(Chalf + row * Ndim + col) =
                        *reinterpret_cast<const uint32_t*>(h);
                } else {
                    float2 o; o.x = v0; o.y = v1;
                    *reinterpret_cast<float2*>(Cout + row * Ndim + col) = o;
                }
            }
        }
    }
}

// ======================= launch =======================
extern "C" void kernel_launch(void* const* d_in, const int* in_sizes, int n_in,
                              void* d_out, int out_size) {
    const float* x  = (const float*)d_in[0];
    const float* w1 = (const float*)d_in[1];
    const float* w2 = (const float*)d_in[2];
    float* out = (float*)d_out;
    (void)in_sizes; (void)n_in; (void)out_size;

    cudaFuncSetAttribute(hmma_gemm_kernel<true>,
                         cudaFuncAttributeMaxDynamicSharedMemorySize, SMEM_BYTES);
    cudaFuncSetAttribute(hmma_gemm_kernel<false>,
                         cudaFuncAttributeMaxDynamicSharedMemorySize, SMEM_BYTES);

    __half *xh, *w1t, *w2t, *hid;
    cudaGetSymbolAddress((void**)&xh,  g_x);
    cudaGetSymbolAddress((void**)&w1t, g_w1);
    cudaGetSymbolAddress((void**)&w2t, g_w2);
    cudaGetSymbolAddress((void**)&hid, g_h);

    // 1) round x -> fp16
    {
        size_t n4 = (size_t)E * M * D / 4;
        round_kernel<<<(unsigned)(n4 / 256), 256>>>((const float4*)x, xh);
    }
    // 2) transpose+round w1: [E][D][H] -> [E][H][D] fp16
    {
        dim3 grid(H / 32, D / 32, E), blk(32, 8);
        transpose_round_kernel<<<grid, blk>>>(w1, w1t, D, H);
    }
    // 3) transpose+round w2: [E][H][D] -> [E][D][H] fp16
    {
        dim3 grid(D / 32, H / 32, E), blk(32, 8);
        transpose_round_kernel<<<grid, blk>>>(w2, w2t, H, D);
    }
    // 4) GEMM1 + GELU -> hidden fp16  (M x H, K = D)
    {
        dim3 grid(H / BN, M / 128, E);
        hmma_gemm_kernel<true><<<grid, 256, SMEM_BYTES>>>(
            xh, w1t, nullptr, hid, M, H, D);
    }
    // 5) GEMM2 -> out fp32  (M x D, K = H)
    {
        dim3 grid(D / BN, M / 128, E);
        hmma_gemm_kernel<false><<<grid, 256, SMEM_BYTES>>>(
            hid, w2t, out, nullptr, M, D, H);
    }
}

// round 14
// speedup vs baseline: 2.4910x; 1.0674x over previous
#include <cuda_runtime.h>
#include <cuda_fp16.h>
#include <cstdint>
#include <math.h>

// out = gelu_exact(x @ w1) @ w2 per expert.
// Plain fp16 HMMA (mma.sync m16n8k16 f16, fp32 accum), all operands rounded
// to fp16. rel_err ~4e-4 (under 1e-3 with margin).
// CTA 128x128, 4 warps (2x2) of 64x64, 2 CTAs/SM: best crossbar ratio
// (8 ldsm per 32 MMAs) AND interleaved barrier seams.

static constexpr int E = 8;
static constexpr int M = 2048;
static constexpr int D = 1024;
static constexpr int H = 4096;

// ---- device scratch (no runtime allocation allowed) ----
__device__ __align__(256) __half g_x [(size_t)E * M * D];  // x fp16
__device__ __align__(256) __half g_w1[(size_t)E * H * D];  // [E][H][D] K-major
__device__ __align__(256) __half g_w2[(size_t)E * D * H];  // [E][D][H] K-major
__device__ __align__(256) __half g_h [(size_t)E * M * H];  // hidden fp16 [E][M][H]

// ======================= helpers =======================
__device__ __forceinline__ uint32_t smem_u32(const void* p) {
    uint32_t a;
    asm("{ .reg .u64 t; cvta.to.shared.u64 t, %1; cvt.u32.u64 %0, t; }" : "=r"(a) : "l"(p));
    return a;
}
__device__ __forceinline__ void cp16(uint32_t dst, const void* src) {
    asm volatile("cp.async.cg.shared.global [%0], [%1], 16;" :: "r"(dst), "l"(src));
}
#define CP_COMMIT() asm volatile("cp.async.commit_group;" ::: "memory")

__device__ __forceinline__ void ldsm_x4(uint32_t& r0, uint32_t& r1, uint32_t& r2,
                                        uint32_t& r3, uint32_t addr) {
    asm volatile("ldmatrix.sync.aligned.m8n8.x4.shared.b16 {%0,%1,%2,%3}, [%4];"
                 : "=r"(r0), "=r"(r1), "=r"(r2), "=r"(r3) : "r"(addr));
}
__device__ __forceinline__ void mma_f16(float& d0, float& d1, float& d2, float& d3,
                                        uint32_t a0, uint32_t a1, uint32_t a2, uint32_t a3,
                                        uint32_t b0, uint32_t b1) {
    asm volatile(
        "mma.sync.aligned.m16n8k16.row.col.f32.f16.f16.f32 "
        "{%0,%1,%2,%3}, {%4,%5,%6,%7}, {%8,%9}, {%0,%1,%2,%3};"
        : "+f"(d0), "+f"(d1), "+f"(d2), "+f"(d3)
        : "r"(a0), "r"(a1), "r"(a2), "r"(a3), "r"(b0), "r"(b1));
}

// SW128 swizzle: XOR quad column (bits 6:4) with row mod 8 (bits 9:7)
__device__ __forceinline__ uint32_t swz(uint32_t off) { return off ^ ((off >> 3) & 0x70); }

__device__ __forceinline__ float gelu_exact(float x) {
    return 0.5f * x * (1.0f + erff(x * 0.7071067811865476f));
}

// ======================= conversion kernels =======================
__global__ void round_kernel(const float4* __restrict__ in, __half* __restrict__ out) {
    size_t i = (size_t)blockIdx.x * blockDim.x + threadIdx.x;
    float4 v = in[i];
    __half h[4] = {__float2half_rn(v.x), __float2half_rn(v.y),
                   __float2half_rn(v.z), __float2half_rn(v.w)};
    *reinterpret_cast<uint2*>(out + i * 4) = *reinterpret_cast<const uint2*>(h);
}

// in [R][C] per expert -> out [C][R] fp16
__global__ void transpose_round_kernel(const float* __restrict__ in,
                                       __half* __restrict__ o,
                                       int R, int C) {
    __shared__ float tile[32][33];
    const float* src = in + (size_t)blockIdx.z * R * C;
    __half* dst = o + (size_t)blockIdx.z * R * C;
    int c0 = blockIdx.x * 32, r0 = blockIdx.y * 32;
    int tx = threadIdx.x, ty = threadIdx.y;
#pragma unroll
    for (int i = ty; i < 32; i += 8)
        tile[i][tx] = src[(size_t)(r0 + i) * C + c0 + tx];
    __syncthreads();
#pragma unroll
    for (int i = ty; i < 32; i += 8)
        dst[(size_t)(c0 + i) * R + r0 + tx] = __float2half_rn(tile[tx][i]);
}

// ======================= HMMA GEMM =======================
// CTA tile 128x128, BK=64. 4 warps (2m x 2n), warp tile 64x64. 2 CTAs/SM.
// SMEM per stage: A 128x128B = 16KB, B 128x128B = 16KB. 2 stages = 64KB/CTA.
static constexpr int BK = 64;
static constexpr int BN = 128;
static constexpr int A_BYTES = 128 * 128;                 // 16384
static constexpr int B_BYTES = 128 * 128;                 // 16384
static constexpr int B_OFF = A_BYTES;
static constexpr int STAGE_BYTES = A_BYTES + B_BYTES;     // 32768
static constexpr int SMEM_BYTES = 2 * STAGE_BYTES;        // 65536

template <bool GELU_HALF_OUT>
__global__ __launch_bounds__(128, 2)
void hmma_gemm_kernel(const __half* __restrict__ A,
                      const __half* __restrict__ B,
                      float* __restrict__ Cout,
                      __half* __restrict__ Chalf,
                      int Mdim, int Ndim, int Kdim) {
    extern __shared__ char smem[];
    const uint32_t sb = smem_u32(smem);

    const int tid = threadIdx.x;
    const int wid = tid >> 5;
    const int lane = tid & 31;
    const int e = blockIdx.z;
    const int brow = blockIdx.y * 128;
    const int bcol = blockIdx.x * BN;

    const size_t mk = (size_t)Mdim * Kdim, nk = (size_t)Ndim * Kdim;
    const size_t mn = (size_t)Mdim * Ndim;
    A += (size_t)e * mk;
    B += (size_t)e * nk;
    if (GELU_HALF_OUT) Chalf += (size_t)e * mn;
    else               Cout  += (size_t)e * mn;

    const int warp_m = (wid >> 1) * 64;   // 0, 64
    const int warp_n = (wid & 1) * 64;    // 0, 64

    // per-lane ldmatrix row/quad decomposition
    const int lr = lane & 7, lg = lane >> 3;
    const int a_row = lr + (lg & 1) * 8;     // row within 16-row tile
    const int a_q   = lg >> 1;               // k8-half within k16
    const int b_row = lr + (lg >> 1) * 8;    // row within 16-n-row pair
    const int b_q   = lg & 1;

    float acc[4][8][4];
#pragma unroll
    for (int i = 0; i < 4; i++)
#pragma unroll
        for (int j = 0; j < 8; j++)
#pragma unroll
            for (int r = 0; r < 4; r++) acc[i][j][r] = 0.0f;

    const int NK = Kdim / BK;

    // STS per stage: A 1024 quads + B 1024 quads; 128 threads -> 8+8 cp16/thread.
    auto load_stage = [&](int kc, int stage) {
        const int k0 = kc * BK;
        const uint32_t stg = sb + stage * STAGE_BYTES;
#pragma unroll
        for (int p = 0; p < 8; p++) {
            const int qi = tid + p * 128;
            const int r = qi >> 3, c = qi & 7;
            cp16(stg + swz(r * 128 + c * 16),
                 A + (size_t)(brow + r) * Kdim + k0 + c * 8);
        }
#pragma unroll
        for (int p = 0; p < 8; p++) {
            const int qi = tid + p * 128;
            const int r = qi >> 3, c = qi & 7;
            cp16(stg + B_OFF + swz(r * 128 + c * 16),
                 B + (size_t)(bcol + r) * Kdim + k0 + c * 8);
        }
        CP_COMMIT();
    };

    load_stage(0, 0);

    for (int k = 0; k < NK; k++) {
        const int s = k & 1;
        const uint32_t stg = sb + s * STAGE_BYTES;
        asm volatile("cp.async.wait_group 0;" ::: "memory");
        __syncthreads();
        if (k + 1 < NK) load_stage(k + 1, s ^ 1);

#pragma unroll
        for (int s16 = 0; s16 < 4; s16++) {       // four k16 steps in BK=64
            const int aq = 2 * s16 + a_q;          // A quad col 0..7
            const int bq = 2 * s16 + b_q;          // B quad col 0..7

            uint32_t b[8][2];
#pragma unroll
            for (int jp = 0; jp < 4; jp++) {
                const uint32_t brow_off = (warp_n + b_row + jp * 16) * 128;
                ldsm_x4(b[2 * jp][0], b[2 * jp][1], b[2 * jp + 1][0], b[2 * jp + 1][1],
                        stg + B_OFF + swz(brow_off + bq * 16));
            }
            uint32_t a[4][4];
#pragma unroll
            for (int i = 0; i < 4; i++)
                ldsm_x4(a[i][0], a[i][1], a[i][2], a[i][3],
                        stg + swz((warp_m + a_row + i * 16) * 128 + aq * 16));
            // 32 independent MMAs per k16 step
#pragma unroll
            for (int i = 0; i < 4; i++)
#pragma unroll
                for (int j = 0; j < 8; j++)
                    mma_f16(acc[i][j][0], acc[i][j][1], acc[i][j][2], acc[i][j][3],
                            a[i][0], a[i][1], a[i][2], a[i][3], b[j][0], b[j][1]);
        }
    }

    // ---- epilogue ----
    const int lrow = lane >> 2;          // 0..7
    const int lcol = (lane & 3) * 2;     // 0,2,4,6
#pragma unroll
    for (int i = 0; i < 4; i++) {
#pragma unroll
        for (int hh = 0; hh < 2; hh++) {
            const size_t row = (size_t)(brow + warp_m + i * 16 + lrow + hh * 8);
#pragma unroll
            for (int j = 0; j < 8; j++) {
                const size_t col = (size_t)(bcol + warp_n + j * 8 + lcol);
                float v0 = acc[i][j][2 * hh];
                float v1 = acc[i][j][2 * hh + 1];
                if (GELU_HALF_OUT) {
                    __half h[2] = {__float2half_rn(gelu_exact(v0)),
                                   __float2half_rn(gelu_exact(v1))};
                    *reinterpret_cast<uint32_t*>(Chalf + row * Ndim + col) =
                        *reinterpret_cast<const uint32_t*>(h);
                } else {
                    float2 o; o.x = v0; o.y = v1;
                    *reinterpret_cast<float2*>(Cout + row * Ndim + col) = o;
                }
            }
        }
    }
}

// ======================= launch =======================
extern "C" void kernel_launch(void* const* d_in, const int* in_sizes, int n_in,
                              void* d_out, int out_size) {
    const float* x  = (const float*)d_in[0];
    const float* w1 = (const float*)d_in[1];
    const float* w2 = (const float*)d_in[2];
    float* out = (float*)d_out;
    (void)in_sizes; (void)n_in; (void)out_size;

    cudaFuncSetAttribute(hmma_gemm_kernel<true>,
                         cudaFuncAttributeMaxDynamicSharedMemorySize, SMEM_BYTES);
    cudaFuncSetAttribute(hmma_gemm_kernel<false>,
                         cudaFuncAttributeMaxDynamicSharedMemorySize, SMEM_BYTES);

    __half *xh, *w1t, *w2t, *hid;
    cudaGetSymbolAddress((void**)&xh,  g_x);
    cudaGetSymbolAddress((void**)&w1t, g_w1);
    cudaGetSymbolAddress((void**)&w2t, g_w2);
    cudaGetSymbolAddress((void**)&hid, g_h);

    // 1) round x -> fp16
    {
        size_t n4 = (size_t)E * M * D / 4;
        round_kernel<<<(unsigned)(n4 / 256), 256>>>((const float4*)x, xh);
    }
    // 2) transpose+round w1: [E][D][H] -> [E][H][D] fp16
    {
        dim3 grid(H / 32, D / 32, E), blk(32, 8);
        transpose_round_kernel<<<grid, blk>>>(w1, w1t, D, H);
    }
    // 3) transpose+round w2: [E][H][D] -> [E][D][H] fp16
    {
        dim3 grid(D / 32, H / 32, E), blk(32, 8);
        transpose_round_kernel<<<grid, blk>>>(w2, w2t, H, D);
    }
    // 4) GEMM1 + GELU -> hidden fp16  (M x H, K = D)
    {
        dim3 grid(H / BN, M / 128, E);
        hmma_gemm_kernel<true><<<grid, 128, SMEM_BYTES>>>(
            xh, w1t, nullptr, hid, M, H, D);
    }
    // 5) GEMM2 -> out fp32  (M x D, K = H)
    {
        dim3 grid(D / BN, M / 128, E);
        hmma_gemm_kernel<false><<<grid, 128, SMEM_BYTES>>>(
            hid, w2t, out, nullptr, M, D, H);
    }
}

// round 15
// speedup vs baseline: 2.5771x; 1.0346x over previous
#include <cuda_runtime.h>
#include <cuda_fp16.h>
#include <cstdint>
#include <math.h>

// out = gelu_exact(x @ w1) @ w2 per expert.
// Plain fp16 HMMA (mma.sync m16n8k16 f16, fp32 accum). rel_err ~4e-4.
// CTA 128x128, 8 warps (2m x 4n) of 64x32, 256 threads, 2 CTAs/SM:
// 4 warps/SMSP for latency hiding (R12-proven) + 0.75 crossbar ratio.

static constexpr int E = 8;
static constexpr int M = 2048;
static constexpr int D = 1024;
static constexpr int H = 4096;

// ---- device scratch (no runtime allocation allowed) ----
__device__ __align__(256) __half g_x [(size_t)E * M * D];  // x fp16
__device__ __align__(256) __half g_w1[(size_t)E * H * D];  // [E][H][D] K-major
__device__ __align__(256) __half g_w2[(size_t)E * D * H];  // [E][D][H] K-major
__device__ __align__(256) __half g_h [(size_t)E * M * H];  // hidden fp16 [E][M][H]

// ======================= helpers =======================
__device__ __forceinline__ uint32_t smem_u32(const void* p) {
    uint32_t a;
    asm("{ .reg .u64 t; cvta.to.shared.u64 t, %1; cvt.u32.u64 %0, t; }" : "=r"(a) : "l"(p));
    return a;
}
__device__ __forceinline__ void cp16(uint32_t dst, const void* src) {
    asm volatile("cp.async.cg.shared.global [%0], [%1], 16;" :: "r"(dst), "l"(src));
}
#define CP_COMMIT() asm volatile("cp.async.commit_group;" ::: "memory")

__device__ __forceinline__ void ldsm_x4(uint32_t& r0, uint32_t& r1, uint32_t& r2,
                                        uint32_t& r3, uint32_t addr) {
    asm volatile("ldmatrix.sync.aligned.m8n8.x4.shared.b16 {%0,%1,%2,%3}, [%4];"
                 : "=r"(r0), "=r"(r1), "=r"(r2), "=r"(r3) : "r"(addr));
}
__device__ __forceinline__ void mma_f16(float& d0, float& d1, float& d2, float& d3,
                                        uint32_t a0, uint32_t a1, uint32_t a2, uint32_t a3,
                                        uint32_t b0, uint32_t b1) {
    asm volatile(
        "mma.sync.aligned.m16n8k16.row.col.f32.f16.f16.f32 "
        "{%0,%1,%2,%3}, {%4,%5,%6,%7}, {%8,%9}, {%0,%1,%2,%3};"
        : "+f"(d0), "+f"(d1), "+f"(d2), "+f"(d3)
        : "r"(a0), "r"(a1), "r"(a2), "r"(a3), "r"(b0), "r"(b1));
}

// SW128 swizzle: XOR quad column (bits 6:4) with row mod 8 (bits 9:7)
__device__ __forceinline__ uint32_t swz(uint32_t off) { return off ^ ((off >> 3) & 0x70); }

__device__ __forceinline__ float gelu_exact(float x) {
    return 0.5f * x * (1.0f + erff(x * 0.7071067811865476f));
}

// ======================= conversion kernels =======================
__global__ void round_kernel(const float4* __restrict__ in, __half* __restrict__ out) {
    size_t i = (size_t)blockIdx.x * blockDim.x + threadIdx.x;
    float4 v = in[i];
    __half h[4] = {__float2half_rn(v.x), __float2half_rn(v.y),
                   __float2half_rn(v.z), __float2half_rn(v.w)};
    *reinterpret_cast<uint2*>(out + i * 4) = *reinterpret_cast<const uint2*>(h);
}

// in [R][C] per expert -> out [C][R] fp16
__global__ void transpose_round_kernel(const float* __restrict__ in,
                                       __half* __restrict__ o,
                                       int R, int C) {
    __shared__ float tile[32][33];
    const float* src = in + (size_t)blockIdx.z * R * C;
    __half* dst = o + (size_t)blockIdx.z * R * C;
    int c0 = blockIdx.x * 32, r0 = blockIdx.y * 32;
    int tx = threadIdx.x, ty = threadIdx.y;
#pragma unroll
    for (int i = ty; i < 32; i += 8)
        tile[i][tx] = src[(size_t)(r0 + i) * C + c0 + tx];
    __syncthreads();
#pragma unroll
    for (int i = ty; i < 32; i += 8)
        dst[(size_t)(c0 + i) * R + r0 + tx] = __float2half_rn(tile[tx][i]);
}

// ======================= HMMA GEMM =======================
// CTA tile 128x128, BK=64. 8 warps (2m x 4n), warp tile 64x32. 2 CTAs/SM.
// SMEM per stage: A 128x128B = 16KB, B 128x128B = 16KB. 2 stages = 64KB/CTA.
static constexpr int BK = 64;
static constexpr int BN = 128;
static constexpr int A_BYTES = 128 * 128;                 // 16384
static constexpr int B_BYTES = 128 * 128;                 // 16384
static constexpr int B_OFF = A_BYTES;
static constexpr int STAGE_BYTES = A_BYTES + B_BYTES;     // 32768
static constexpr int SMEM_BYTES = 2 * STAGE_BYTES;        // 65536

template <bool GELU_HALF_OUT>
__global__ __launch_bounds__(256, 2)
void hmma_gemm_kernel(const __half* __restrict__ A,
                      const __half* __restrict__ B,
                      float* __restrict__ Cout,
                      __half* __restrict__ Chalf,
                      int Mdim, int Ndim, int Kdim) {
    extern __shared__ char smem[];
    const uint32_t sb = smem_u32(smem);

    const int tid = threadIdx.x;
    const int wid = tid >> 5;
    const int lane = tid & 31;
    const int e = blockIdx.z;
    const int brow = blockIdx.y * 128;
    const int bcol = blockIdx.x * BN;

    const size_t mk = (size_t)Mdim * Kdim, nk = (size_t)Ndim * Kdim;
    const size_t mn = (size_t)Mdim * Ndim;
    A += (size_t)e * mk;
    B += (size_t)e * nk;
    if (GELU_HALF_OUT) Chalf += (size_t)e * mn;
    else               Cout  += (size_t)e * mn;

    const int warp_m = (wid >> 2) * 64;   // 0, 64
    const int warp_n = (wid & 3) * 32;    // 0,32,64,96

    // per-lane ldmatrix row/quad decomposition
    const int lr = lane & 7, lg = lane >> 3;
    const int a_row = lr + (lg & 1) * 8;     // row within 16-row tile
    const int a_q   = lg >> 1;               // k8-half within k16
    const int b_row = lr + (lg >> 1) * 8;    // row within 16-n-row pair
    const int b_q   = lg & 1;

    float acc[4][4][4];
#pragma unroll
    for (int i = 0; i < 4; i++)
#pragma unroll
        for (int j = 0; j < 4; j++)
#pragma unroll
            for (int r = 0; r < 4; r++) acc[i][j][r] = 0.0f;

    const int NK = Kdim / BK;

    // STS per stage: A 1024 quads (4/thread) + B 1024 quads (4/thread).
    auto load_stage = [&](int kc, int stage) {
        const int k0 = kc * BK;
        const uint32_t stg = sb + stage * STAGE_BYTES;
#pragma unroll
        for (int p = 0; p < 4; p++) {
            const int qi = tid + p * 256;
            const int r = qi >> 3, c = qi & 7;
            cp16(stg + swz(r * 128 + c * 16),
                 A + (size_t)(brow + r) * Kdim + k0 + c * 8);
        }
#pragma unroll
        for (int p = 0; p < 4; p++) {
            const int qi = tid + p * 256;
            const int r = qi >> 3, c = qi & 7;
            cp16(stg + B_OFF + swz(r * 128 + c * 16),
                 B + (size_t)(bcol + r) * Kdim + k0 + c * 8);
        }
        CP_COMMIT();
    };

    load_stage(0, 0);

    for (int k = 0; k < NK; k++) {
        const int s = k & 1;
        const uint32_t stg = sb + s * STAGE_BYTES;
        asm volatile("cp.async.wait_group 0;" ::: "memory");
        __syncthreads();
        if (k + 1 < NK) load_stage(k + 1, s ^ 1);

#pragma unroll
        for (int s16 = 0; s16 < 4; s16++) {       // four k16 steps in BK=64
            const int aq = 2 * s16 + a_q;          // A quad col 0..7
            const int bq = 2 * s16 + b_q;          // B quad col 0..7

            uint32_t b[4][2];
#pragma unroll
            for (int jp = 0; jp < 2; jp++) {
                const uint32_t brow_off = (warp_n + b_row + jp * 16) * 128;
                ldsm_x4(b[2 * jp][0], b[2 * jp][1], b[2 * jp + 1][0], b[2 * jp + 1][1],
                        stg + B_OFF + swz(brow_off + bq * 16));
            }
            uint32_t a[4][4];
#pragma unroll
            for (int i = 0; i < 4; i++)
                ldsm_x4(a[i][0], a[i][1], a[i][2], a[i][3],
                        stg + swz((warp_m + a_row + i * 16) * 128 + aq * 16));
            // 16 independent MMAs per k16 step
#pragma unroll
            for (int i = 0; i < 4; i++)
#pragma unroll
                for (int j = 0; j < 4; j++)
                    mma_f16(acc[i][j][0], acc[i][j][1], acc[i][j][2], acc[i][j][3],
                            a[i][0], a[i][1], a[i][2], a[i][3], b[j][0], b[j][1]);
        }
    }

    // ---- epilogue ----
    const int lrow = lane >> 2;          // 0..7
    const int lcol = (lane & 3) * 2;     // 0,2,4,6
#pragma unroll
    for (int i = 0; i < 4; i++) {
#pragma unroll
        for (int hh = 0; hh < 2; hh++) {
            const size_t row = (size_t)(brow + warp_m + i * 16 + lrow + hh * 8);
#pragma unroll
            for (int j = 0; j < 4; j++) {
                const size_t col = (size_t)(bcol + warp_n + j * 8 + lcol);
                float v0 = acc[i][j][2 * hh];
                float v1 = acc[i][j][2 * hh + 1];
                if (GELU_HALF_OUT) {
                    __half h[2] = {__float2half_rn(gelu_exact(v0)),
                                   __float2half_rn(gelu_exact(v1))};
                    *reinterpret_cast<uint32_t*>(Chalf + row * Ndim + col) =
                        *reinterpret_cast<const uint32_t*>(h);
                } else {
                    float2 o; o.x = v0; o.y = v1;
                    *reinterpret_cast<float2*>(Cout + row * Ndim + col) = o;
                }
            }
        }
    }
}

// ======================= launch =======================
extern "C" void kernel_launch(void* const* d_in, const int* in_sizes, int n_in,
                              void* d_out, int out_size) {
    const float* x  = (const float*)d_in[0];
    const float* w1 = (const float*)d_in[1];
    const float* w2 = (const float*)d_in[2];
    float* out = (float*)d_out;
    (void)in_sizes; (void)n_in; (void)out_size;

    cudaFuncSetAttribute(hmma_gemm_kernel<true>,
                         cudaFuncAttributeMaxDynamicSharedMemorySize, SMEM_BYTES);
    cudaFuncSetAttribute(hmma_gemm_kernel<false>,
                         cudaFuncAttributeMaxDynamicSharedMemorySize, SMEM_BYTES);

    __half *xh, *w1t, *w2t, *hid;
    cudaGetSymbolAddress((void**)&xh,  g_x);
    cudaGetSymbolAddress((void**)&w1t, g_w1);
    cudaGetSymbolAddress((void**)&w2t, g_w2);
    cudaGetSymbolAddress((void**)&hid, g_h);

    // 1) round x -> fp16
    {
        size_t n4 = (size_t)E * M * D / 4;
        round_kernel<<<(unsigned)(n4 / 256), 256>>>((const float4*)x, xh);
    }
    // 2) transpose+round w1: [E][D][H] -> [E][H][D] fp16
    {
        dim3 grid(H / 32, D / 32, E), blk(32, 8);
        transpose_round_kernel<<<grid, blk>>>(w1, w1t, D, H);
    }
    // 3) transpose+round w2: [E][H][D] -> [E][D][H] fp16
    {
        dim3 grid(D / 32, H / 32, E), blk(32, 8);
        transpose_round_kernel<<<grid, blk>>>(w2, w2t, H, D);
    }
    // 4) GEMM1 + GELU -> hidden fp16  (M x H, K = D)
    {
        dim3 grid(H / BN, M / 128, E);
        hmma_gemm_kernel<true><<<grid, 256, SMEM_BYTES>>>(
            xh, w1t, nullptr, hid, M, H, D);
    }
    // 5) GEMM2 -> out fp32  (M x D, K = H)
    {
        dim3 grid(D / BN, M / 128, E);
        hmma_gemm_kernel<false><<<grid, 256, SMEM_BYTES>>>(
            hid, w2t, out, nullptr, M, D, H);
    }
}

// round 16
// speedup vs baseline: 2.7395x; 1.0630x over previous
#include <cuda_runtime.h>
#include <cuda_fp16.h>
#include <cstdint>
#include <math.h>

// out = gelu_exact(x @ w1) @ w2 per expert.
// Plain fp16 HMMA (mma.sync m16n8k16 f16, fp32 accum). rel_err ~4e-4.
// CTA 128x128, 8 warps (2m x 4n) of 64x32, 256 threads, 2 CTAs/SM.
// B kept in NATIVE layout (k-rows, n contiguous); fragments produced via
// ldmatrix.x4.trans -> no weight transpose prep kernels needed.

static constexpr int E = 8;
static constexpr int M = 2048;
static constexpr int D = 1024;
static constexpr int H = 4096;

// ---- device scratch (no runtime allocation allowed) ----
__device__ __align__(256) __half g_x [(size_t)E * M * D];  // x fp16 [E][M][D]
__device__ __align__(256) __half g_w1[(size_t)E * D * H];  // w1 fp16 native [E][D][H]
__device__ __align__(256) __half g_w2[(size_t)E * H * D];  // w2 fp16 native [E][H][D]
__device__ __align__(256) __half g_h [(size_t)E * M * H];  // hidden fp16 [E][M][H]

// ======================= helpers =======================
__device__ __forceinline__ uint32_t smem_u32(const void* p) {
    uint32_t a;
    asm("{ .reg .u64 t; cvta.to.shared.u64 t, %1; cvt.u32.u64 %0, t; }" : "=r"(a) : "l"(p));
    return a;
}
__device__ __forceinline__ void cp16(uint32_t dst, const void* src) {
    asm volatile("cp.async.cg.shared.global [%0], [%1], 16;" :: "r"(dst), "l"(src));
}
#define CP_COMMIT() asm volatile("cp.async.commit_group;" ::: "memory")

__device__ __forceinline__ void ldsm_x4(uint32_t& r0, uint32_t& r1, uint32_t& r2,
                                        uint32_t& r3, uint32_t addr) {
    asm volatile("ldmatrix.sync.aligned.m8n8.x4.shared.b16 {%0,%1,%2,%3}, [%4];"
                 : "=r"(r0), "=r"(r1), "=r"(r2), "=r"(r3) : "r"(addr));
}
__device__ __forceinline__ void ldsm_x4_trans(uint32_t& r0, uint32_t& r1, uint32_t& r2,
                                              uint32_t& r3, uint32_t addr) {
    asm volatile("ldmatrix.sync.aligned.m8n8.x4.trans.shared.b16 {%0,%1,%2,%3}, [%4];"
                 : "=r"(r0), "=r"(r1), "=r"(r2), "=r"(r3) : "r"(addr));
}
__device__ __forceinline__ void mma_f16(float& d0, float& d1, float& d2, float& d3,
                                        uint32_t a0, uint32_t a1, uint32_t a2, uint32_t a3,
                                        uint32_t b0, uint32_t b1) {
    asm volatile(
        "mma.sync.aligned.m16n8k16.row.col.f32.f16.f16.f32 "
        "{%0,%1,%2,%3}, {%4,%5,%6,%7}, {%8,%9}, {%0,%1,%2,%3};"
        : "+f"(d0), "+f"(d1), "+f"(d2), "+f"(d3)
        : "r"(a0), "r"(a1), "r"(a2), "r"(a3), "r"(b0), "r"(b1));
}

// A tile: 128B rows, SW128 swizzle (quad bits 4-6 ^= row bits 7-9)
__device__ __forceinline__ uint32_t swz(uint32_t off)  { return off ^ ((off >> 3) & 0x70); }
// B tile: 256B rows (k-major), swizzle quad bits 4-6 ^= k bits 8-10
__device__ __forceinline__ uint32_t swzB(uint32_t off) { return off ^ ((off >> 4) & 0x70); }

__device__ __forceinline__ float gelu_exact(float x) {
    return 0.5f * x * (1.0f + erff(x * 0.7071067811865476f));
}

// ======================= conversion kernel =======================
__global__ void round_kernel(const float4* __restrict__ in, __half* __restrict__ out) {
    size_t i = (size_t)blockIdx.x * blockDim.x + threadIdx.x;
    float4 v = in[i];
    __half h[4] = {__float2half_rn(v.x), __float2half_rn(v.y),
                   __float2half_rn(v.z), __float2half_rn(v.w)};
    *reinterpret_cast<uint2*>(out + i * 4) = *reinterpret_cast<const uint2*>(h);
}

// ======================= HMMA GEMM =======================
// CTA tile 128x128, BK=64. 8 warps (2m x 4n), warp tile 64x32. 2 CTAs/SM.
// SMEM per stage: A 128 m-rows x 128B = 16KB (swz),
//                 B 64 k-rows x 256B  = 16KB (swzB). 2 stages = 64KB/CTA.
static constexpr int BK = 64;
static constexpr int BN = 128;
static constexpr int A_BYTES = 128 * 128;                 // 16384
static constexpr int B_BYTES = 64 * 256;                  // 16384
static constexpr int B_OFF = A_BYTES;
static constexpr int STAGE_BYTES = A_BYTES + B_BYTES;     // 32768
static constexpr int SMEM_BYTES = 2 * STAGE_BYTES;        // 65536

template <bool GELU_HALF_OUT>
__global__ __launch_bounds__(256, 2)
void hmma_gemm_kernel(const __half* __restrict__ A,
                      const __half* __restrict__ B,   // native [K][N] rows, n contiguous
                      float* __restrict__ Cout,
                      __half* __restrict__ Chalf,
                      int Mdim, int Ndim, int Kdim) {
    extern __shared__ char smem[];
    const uint32_t sb = smem_u32(smem);

    const int tid = threadIdx.x;
    const int wid = tid >> 5;
    const int lane = tid & 31;
    const int e = blockIdx.z;
    const int brow = blockIdx.y * 128;
    const int bcol = blockIdx.x * BN;

    const size_t mk = (size_t)Mdim * Kdim, nk = (size_t)Ndim * Kdim;
    const size_t mn = (size_t)Mdim * Ndim;
    A += (size_t)e * mk;
    B += (size_t)e * nk;
    if (GELU_HALF_OUT) Chalf += (size_t)e * mn;
    else               Cout  += (size_t)e * mn;

    const int warp_m = (wid >> 2) * 64;   // 0, 64
    const int warp_n = (wid & 3) * 32;    // 0,32,64,96

    // per-lane ldmatrix decomposition
    const int lr = lane & 7, lg = lane >> 3;
    // A (non-trans): row within 16-row tile + k8 quad
    const int a_row = lr + (lg & 1) * 8;
    const int a_q   = lg >> 1;
    // B (trans): tile lg -> k8-half = lg&1, n8-half = lg>>1 ; row lr = k row
    const int b_k8  = (lg & 1) * 8 + lr;            // k row within k16
    const int b_n8  = (lg >> 1) * 8;                // n offset within n16

    float acc[4][4][4];
#pragma unroll
    for (int i = 0; i < 4; i++)
#pragma unroll
        for (int j = 0; j < 4; j++)
#pragma unroll
            for (int r = 0; r < 4; r++) acc[i][j][r] = 0.0f;

    const int NK = Kdim / BK;

    // STS per stage: A 1024 quads (4/thread) + B 1024 quads (4/thread).
    auto load_stage = [&](int kc, int stage) {
        const int k0 = kc * BK;
        const uint32_t stg = sb + stage * STAGE_BYTES;
#pragma unroll
        for (int p = 0; p < 4; p++) {      // A: m-rows of 128B
            const int qi = tid + p * 256;
            const int r = qi >> 3, c = qi & 7;
            cp16(stg + swz(r * 128 + c * 16),
                 A + (size_t)(brow + r) * Kdim + k0 + c * 8);
        }
#pragma unroll
        for (int p = 0; p < 4; p++) {      // B: k-rows of 256B (16 quads each)
            const int qi = tid + p * 256;
            const int r = qi >> 4, c = qi & 15;
            cp16(stg + B_OFF + swzB(r * 256 + c * 16),
                 B + (size_t)(k0 + r) * Ndim + bcol + c * 8);
        }
        CP_COMMIT();
    };

    load_stage(0, 0);

    for (int k = 0; k < NK; k++) {
        const int s = k & 1;
        const uint32_t stg = sb + s * STAGE_BYTES;
        asm volatile("cp.async.wait_group 0;" ::: "memory");
        __syncthreads();
        if (k + 1 < NK) load_stage(k + 1, s ^ 1);

#pragma unroll
        for (int s16 = 0; s16 < 4; s16++) {       // four k16 steps in BK=64
            const int aq = 2 * s16 + a_q;          // A quad col 0..7

            uint32_t b[4][2];
#pragma unroll
            for (int jp = 0; jp < 2; jp++) {
                // tiles: (k0:8,n_j),(k8:16,n_j),(k0:8,n_j+8),(k8:16,n_j+8)
                const uint32_t boff =
                    (uint32_t)(s16 * 16 + b_k8) * 256 + (warp_n + jp * 16 + b_n8) * 2;
                ldsm_x4_trans(b[2 * jp][0], b[2 * jp][1], b[2 * jp + 1][0], b[2 * jp + 1][1],
                              stg + B_OFF + swzB(boff));
            }
            uint32_t a[4][4];
#pragma unroll
            for (int i = 0; i < 4; i++)
                ldsm_x4(a[i][0], a[i][1], a[i][2], a[i][3],
                        stg + swz((warp_m + a_row + i * 16) * 128 + aq * 16));
            // 16 independent MMAs per k16 step
#pragma unroll
            for (int i = 0; i < 4; i++)
#pragma unroll
                for (int j = 0; j < 4; j++)
                    mma_f16(acc[i][j][0], acc[i][j][1], acc[i][j][2], acc[i][j][3],
                            a[i][0], a[i][1], a[i][2], a[i][3], b[j][0], b[j][1]);
        }
    }

    // ---- epilogue ----
    const int lrow = lane >> 2;          // 0..7
    const int lcol = (lane & 3) * 2;     // 0,2,4,6
#pragma unroll
    for (int i = 0; i < 4; i++) {
#pragma unroll
        for (int hh = 0; hh < 2; hh++) {
            const size_t row = (size_t)(brow + warp_m + i * 16 + lrow + hh * 8);
#pragma unroll
            for (int j = 0; j < 4; j++) {
                const size_t col = (size_t)(bcol + warp_n + j * 8 + lcol);
                float v0 = acc[i][j][2 * hh];
                float v1 = acc[i][j][2 * hh + 1];
                if (GELU_HALF_OUT) {
                    __half h[2] = {__float2half_rn(gelu_exact(v0)),
                                   __float2half_rn(gelu_exact(v1))};
                    *reinterpret_cast<uint32_t*>(Chalf + row * Ndim + col) =
                        *reinterpret_cast<const uint32_t*>(h);
                } else {
                    float2 o; o.x = v0; o.y = v1;
                    *reinterpret_cast<float2*>(Cout + row * Ndim + col) = o;
                }
            }
        }
    }
}

// ======================= launch =======================
extern "C" void kernel_launch(void* const* d_in, const int* in_sizes, int n_in,
                              void* d_out, int out_size) {
    const float* x  = (const float*)d_in[0];
    const float* w1 = (const float*)d_in[1];
    const float* w2 = (const float*)d_in[2];
    float* out = (float*)d_out;
    (void)in_sizes; (void)n_in; (void)out_size;

    cudaFuncSetAttribute(hmma_gemm_kernel<true>,
                         cudaFuncAttributeMaxDynamicSharedMemorySize, SMEM_BYTES);
    cudaFuncSetAttribute(hmma_gemm_kernel<false>,
                         cudaFuncAttributeMaxDynamicSharedMemorySize, SMEM_BYTES);

    __half *xh, *w1h, *w2h, *hid;
    cudaGetSymbolAddress((void**)&xh,  g_x);
    cudaGetSymbolAddress((void**)&w1h, g_w1);
    cudaGetSymbolAddress((void**)&w2h, g_w2);
    cudaGetSymbolAddress((void**)&hid, g_h);

    // 1) round x, w1, w2 -> fp16 (element-wise, native layouts)
    {
        size_t n4 = (size_t)E * M * D / 4;
        round_kernel<<<(unsigned)(n4 / 256), 256>>>((const float4*)x, xh);
    }
    {
        size_t n4 = (size_t)E * D * H / 4;
        round_kernel<<<(unsigned)(n4 / 256), 256>>>((const float4*)w1, w1h);
    }
    {
        size_t n4 = (size_t)E * H * D / 4;
        round_kernel<<<(unsigned)(n4 / 256), 256>>>((const float4*)w2, w2h);
    }
    // 2) GEMM1 + GELU -> hidden fp16  (M x H, K = D), B = w1 native [D][H]
    {
        dim3 grid(H / BN, M / 128, E);
        hmma_gemm_kernel<true><<<grid, 256, SMEM_BYTES>>>(
            xh, w1h, nullptr, hid, M, H, D);
    }
    // 3) GEMM2 -> out fp32  (M x D, K = H), B = w2 native [H][D]
    {
        dim3 grid(D / BN, M / 128, E);
        hmma_gemm_kernel<false><<<grid, 256, SMEM_BYTES>>>(
            hid, w2h, out, nullptr, M, D, H);
    }
}

// round 17
// speedup vs baseline: 2.7473x; 1.0028x over previous
#include <cuda_runtime.h>
#include <cuda_fp16.h>
#include <cstdint>
#include <math.h>

// out = gelu_exact(x @ w1) @ w2 per expert.
// Plain fp16 HMMA (mma.sync m16n8k16 f16, fp32 accum). rel_err ~4e-4.
// CTA 128x128, 8 warps (2m x 4n) of 64x32, 256 threads, 2 CTAs/SM.
// B in NATIVE layout (k-rows, n contiguous) via ldmatrix.x4.trans.
// 3-stage cp.async pipeline, prefetch distance 2, wait_group 1.

static constexpr int E = 8;
static constexpr int M = 2048;
static constexpr int D = 1024;
static constexpr int H = 4096;

// ---- device scratch (no runtime allocation allowed) ----
__device__ __align__(256) __half g_x [(size_t)E * M * D];  // x fp16 [E][M][D]
__device__ __align__(256) __half g_w1[(size_t)E * D * H];  // w1 fp16 native [E][D][H]
__device__ __align__(256) __half g_w2[(size_t)E * H * D];  // w2 fp16 native [E][H][D]
__device__ __align__(256) __half g_h [(size_t)E * M * H];  // hidden fp16 [E][M][H]

// ======================= helpers =======================
__device__ __forceinline__ uint32_t smem_u32(const void* p) {
    uint32_t a;
    asm("{ .reg .u64 t; cvta.to.shared.u64 t, %1; cvt.u32.u64 %0, t; }" : "=r"(a) : "l"(p));
    return a;
}
__device__ __forceinline__ void cp16(uint32_t dst, const void* src) {
    asm volatile("cp.async.cg.shared.global [%0], [%1], 16;" :: "r"(dst), "l"(src));
}
#define CP_COMMIT() asm volatile("cp.async.commit_group;" ::: "memory")

__device__ __forceinline__ void ldsm_x4(uint32_t& r0, uint32_t& r1, uint32_t& r2,
                                        uint32_t& r3, uint32_t addr) {
    asm volatile("ldmatrix.sync.aligned.m8n8.x4.shared.b16 {%0,%1,%2,%3}, [%4];"
                 : "=r"(r0), "=r"(r1), "=r"(r2), "=r"(r3) : "r"(addr));
}
__device__ __forceinline__ void ldsm_x4_trans(uint32_t& r0, uint32_t& r1, uint32_t& r2,
                                              uint32_t& r3, uint32_t addr) {
    asm volatile("ldmatrix.sync.aligned.m8n8.x4.trans.shared.b16 {%0,%1,%2,%3}, [%4];"
                 : "=r"(r0), "=r"(r1), "=r"(r2), "=r"(r3) : "r"(addr));
}
__device__ __forceinline__ void mma_f16(float& d0, float& d1, float& d2, float& d3,
                                        uint32_t a0, uint32_t a1, uint32_t a2, uint32_t a3,
                                        uint32_t b0, uint32_t b1) {
    asm volatile(
        "mma.sync.aligned.m16n8k16.row.col.f32.f16.f16.f32 "
        "{%0,%1,%2,%3}, {%4,%5,%6,%7}, {%8,%9}, {%0,%1,%2,%3};"
        : "+f"(d0), "+f"(d1), "+f"(d2), "+f"(d3)
        : "r"(a0), "r"(a1), "r"(a2), "r"(a3), "r"(b0), "r"(b1));
}

// A tile: 128B rows, SW128 swizzle (quad bits 4-6 ^= row bits 7-9)
__device__ __forceinline__ uint32_t swz(uint32_t off)  { return off ^ ((off >> 3) & 0x70); }
// B tile: 256B rows (k-major), swizzle quad bits 4-6 ^= k bits 8-10
__device__ __forceinline__ uint32_t swzB(uint32_t off) { return off ^ ((off >> 4) & 0x70); }

__device__ __forceinline__ float gelu_exact(float x) {
    return 0.5f * x * (1.0f + erff(x * 0.7071067811865476f));
}

// ======================= conversion kernel =======================
__global__ void round_kernel(const float4* __restrict__ in, __half* __restrict__ out) {
    size_t i = (size_t)blockIdx.x * blockDim.x + threadIdx.x;
    float4 v = in[i];
    __half h[4] = {__float2half_rn(v.x), __float2half_rn(v.y),
                   __float2half_rn(v.z), __float2half_rn(v.w)};
    *reinterpret_cast<uint2*>(out + i * 4) = *reinterpret_cast<const uint2*>(h);
}

// ======================= HMMA GEMM =======================
// CTA tile 128x128, BK=64. 8 warps (2m x 4n), warp tile 64x32. 2 CTAs/SM.
// SMEM per stage: A 128 m-rows x 128B = 16KB (swz),
//                 B 64 k-rows x 256B  = 16KB (swzB). 3 stages = 96KB/CTA.
static constexpr int BK = 64;
static constexpr int BN = 128;
static constexpr int A_BYTES = 128 * 128;                 // 16384
static constexpr int B_BYTES = 64 * 256;                  // 16384
static constexpr int B_OFF = A_BYTES;
static constexpr int STAGE_BYTES = A_BYTES + B_BYTES;     // 32768
static constexpr int STAGES = 3;
static constexpr int SMEM_BYTES = STAGES * STAGE_BYTES;   // 98304

template <bool GELU_HALF_OUT>
__global__ __launch_bounds__(256, 2)
void hmma_gemm_kernel(const __half* __restrict__ A,
                      const __half* __restrict__ B,   // native [K][N] rows, n contiguous
                      float* __restrict__ Cout,
                      __half* __restrict__ Chalf,
                      int Mdim, int Ndim, int Kdim) {
    extern __shared__ char smem[];
    const uint32_t sb = smem_u32(smem);

    const int tid = threadIdx.x;
    const int wid = tid >> 5;
    const int lane = tid & 31;
    const int e = blockIdx.z;
    const int brow = blockIdx.y * 128;
    const int bcol = blockIdx.x * BN;

    const size_t mk = (size_t)Mdim * Kdim, nk = (size_t)Ndim * Kdim;
    const size_t mn = (size_t)Mdim * Ndim;
    A += (size_t)e * mk;
    B += (size_t)e * nk;
    if (GELU_HALF_OUT) Chalf += (size_t)e * mn;
    else               Cout  += (size_t)e * mn;

    const int warp_m = (wid >> 2) * 64;   // 0, 64
    const int warp_n = (wid & 3) * 32;    // 0,32,64,96

    // per-lane ldmatrix decomposition
    const int lr = lane & 7, lg = lane >> 3;
    // A (non-trans): row within 16-row tile + k8 quad
    const int a_row = lr + (lg & 1) * 8;
    const int a_q   = lg >> 1;
    // B (trans): k8-half = lg&1, n8-half = lg>>1 ; row lr = k row
    const int b_k8  = (lg & 1) * 8 + lr;            // k row within k16
    const int b_n8  = (lg >> 1) * 8;                // n offset within n16

    float acc[4][4][4];
#pragma unroll
    for (int i = 0; i < 4; i++)
#pragma unroll
        for (int j = 0; j < 4; j++)
#pragma unroll
            for (int r = 0; r < 4; r++) acc[i][j][r] = 0.0f;

    const int NK = Kdim / BK;

    // STS per stage: A 1024 quads (4/thread) + B 1024 quads (4/thread).
    auto load_stage = [&](int kc, int stage) {
        const int k0 = kc * BK;
        const uint32_t stg = sb + stage * STAGE_BYTES;
#pragma unroll
        for (int p = 0; p < 4; p++) {      // A: m-rows of 128B
            const int qi = tid + p * 256;
            const int r = qi >> 3, c = qi & 7;
            cp16(stg + swz(r * 128 + c * 16),
                 A + (size_t)(brow + r) * Kdim + k0 + c * 8);
        }
#pragma unroll
        for (int p = 0; p < 4; p++) {      // B: k-rows of 256B (16 quads each)
            const int qi = tid + p * 256;
            const int r = qi >> 4, c = qi & 15;
            cp16(stg + B_OFF + swzB(r * 256 + c * 16),
                 B + (size_t)(k0 + r) * Ndim + bcol + c * 8);
        }
        CP_COMMIT();
    };

    load_stage(0, 0);
    if (NK > 1) load_stage(1, 1);

    int s = 0;
    for (int k = 0; k < NK; k++) {
        const uint32_t stg = sb + s * STAGE_BYTES;
        // chunk k's group is complete once at most the newest (k+1) remains
        if (k + 1 < NK) asm volatile("cp.async.wait_group 1;" ::: "memory");
        else            asm volatile("cp.async.wait_group 0;" ::: "memory");
        __syncthreads();
        // prefetch chunk k+2 into the stage consumed at iteration k-1
        if (k + 2 < NK) {
            int ns = s + 2; if (ns >= STAGES) ns -= STAGES;
            load_stage(k + 2, ns);
        }

#pragma unroll
        for (int s16 = 0; s16 < 4; s16++) {       // four k16 steps in BK=64
            const int aq = 2 * s16 + a_q;          // A quad col 0..7

            uint32_t a[4][4];
#pragma unroll
            for (int i = 0; i < 4; i++)
                ldsm_x4(a[i][0], a[i][1], a[i][2], a[i][3],
                        stg + swz((warp_m + a_row + i * 16) * 128 + aq * 16));
            uint32_t b[4][2];
#pragma unroll
            for (int jp = 0; jp < 2; jp++) {
                const uint32_t boff =
                    (uint32_t)(s16 * 16 + b_k8) * 256 + (warp_n + jp * 16 + b_n8) * 2;
                ldsm_x4_trans(b[2 * jp][0], b[2 * jp][1], b[2 * jp + 1][0], b[2 * jp + 1][1],
                              stg + B_OFF + swzB(boff));
            }
            // 16 independent MMAs per k16 step
#pragma unroll
            for (int i = 0; i < 4; i++)
#pragma unroll
                for (int j = 0; j < 4; j++)
                    mma_f16(acc[i][j][0], acc[i][j][1], acc[i][j][2], acc[i][j][3],
                            a[i][0], a[i][1], a[i][2], a[i][3], b[j][0], b[j][1]);
        }
        if (++s == STAGES) s = 0;
    }

    // ---- epilogue ----
    const int lrow = lane >> 2;          // 0..7
    const int lcol = (lane & 3) * 2;     // 0,2,4,6
#pragma unroll
    for (int i = 0; i < 4; i++) {
#pragma unroll
        for (int hh = 0; hh < 2; hh++) {
            const size_t row = (size_t)(brow + warp_m + i * 16 + lrow + hh * 8);
#pragma unroll
            for (int j = 0; j < 4; j++) {
                const size_t col = (size_t)(bcol + warp_n + j * 8 + lcol);
                float v0 = acc[i][j][2 * hh];
                float v1 = acc[i][j][2 * hh + 1];
                if (GELU_HALF_OUT) {
                    __half h[2] = {__float2half_rn(gelu_exact(v0)),
                                   __float2half_rn(gelu_exact(v1))};
                    *reinterpret_cast<uint32_t*>(Chalf + row * Ndim + col) =
                        *reinterpret_cast<const uint32_t*>(h);
                } else {
                    float2 o; o.x = v0; o.y = v1;
                    *reinterpret_cast<float2*>(Cout + row * Ndim + col) = o;
                }
            }
        }
    }
}

// ======================= launch =======================
extern "C" void kernel_launch(void* const* d_in, const int* in_sizes, int n_in,
                              void* d_out, int out_size) {
    const float* x  = (const float*)d_in[0];
    const float* w1 = (const float*)d_in[1];
    const float* w2 = (const float*)d_in[2];
    float* out = (float*)d_out;
    (void)in_sizes; (void)n_in; (void)out_size;

    cudaFuncSetAttribute(hmma_gemm_kernel<true>,
                         cudaFuncAttributeMaxDynamicSharedMemorySize, SMEM_BYTES);
    cudaFuncSetAttribute(hmma_gemm_kernel<false>,
                         cudaFuncAttributeMaxDynamicSharedMemorySize, SMEM_BYTES);

    __half *xh, *w1h, *w2h, *hid;
    cudaGetSymbolAddress((void**)&xh,  g_x);
    cudaGetSymbolAddress((void**)&w1h, g_w1);
    cudaGetSymbolAddress((void**)&w2h, g_w2);
    cudaGetSymbolAddress((void**)&hid, g_h);

    // 1) round x, w1, w2 -> fp16 (element-wise, native layouts)
    {
        size_t n4 = (size_t)E * M * D / 4;
        round_kernel<<<(unsigned)(n4 / 256), 256>>>((const float4*)x, xh);
    }
    {
        size_t n4 = (size_t)E * D * H / 4;
        round_kernel<<<(unsigned)(n4 / 256), 256>>>((const float4*)w1, w1h);
    }
    {
        size_t n4 = (size_t)E * H * D / 4;
        round_kernel<<<(unsigned)(n4 / 256), 256>>>((const float4*)w2, w2h);
    }
    // 2) GEMM1 + GELU -> hidden fp16  (M x H, K = D), B = w1 native [D][H]
    {
        dim3 grid(H / BN, M / 128, E);
        hmma_gemm_kernel<true><<<grid, 256, SMEM_BYTES>>>(
            xh, w1h, nullptr, hid, M, H, D);
    }
    // 3) GEMM2 -> out fp32  (M x D, K = H), B = w2 native [H][D]
    {
        dim3 grid(D / BN, M / 128, E);
        hmma_gemm_kernel<false><<<grid, 256, SMEM_BYTES>>>(
            hid, w2h, out, nullptr, M, D, H);
    }
}